// round 12
// baseline (speedup 1.0000x reference)
#include <cuda_runtime.h>

// LFQ: z [4,14,32,32] f32. Codebook = all +-1 bit patterns -> T=0.01 softmax
// factorizes per bit. With em = expf(-400|z_d|): pc = 1/(1+em), po = em*pc,
// flip ratio po/pc = em. pbase = prod(pc) = 1/prod(1+em) (ONE divide);
// sum log1p(em) = logf(prod(1+em)) (ONE log). A soft bit matters only if
// em >= 2^-41 (else every subset's fixed-point emission rounds to 0) ->
// exact pruning; ~2 subsets/token scatter into a u64 fixed-point histogram
// (integer atomics commute => bit-deterministic).
//
// SINGLE kernel, one wave (152 blocks x 128 thr): blocks 0..31 token work,
// blocks 32..151 ring marking; ticket-elected LAST block (others retire,
// nobody spins) runs the reduce tail and self-cleans all scratch for the
// next graph replay.
//
// Output (f32): quantized[57344], commit, entropy_loss, usage, idx_flat[4096].

#define N_TOK 4096
#define DIM   14
#define HW    1024
#define NE    16384
#define QELEMS (N_TOK * DIM)       // 57344
#define FIXSCALE 1099511627776.0   // 2^40
#define FULLM 0xffffffffu
#define EM_MIN 4.5474735088646412e-13f   // 2^-41
#define NBLK 152

__device__ unsigned long long g_hist[NE];     // self-cleaned by tail
__device__ unsigned int       g_bitset[2048]; // self-cleaned by tail
__device__ float              g_wcom[128];    // rewritten every replay
__device__ float              g_went[128];
__device__ unsigned int       g_ticket;       // reset by tail

// ---------------------------------------------------------------------------
__device__ __forceinline__ void emit_subsets_strided(
    unsigned m, float pbase, unsigned idx, const float* __restrict__ ratio,
    unsigned start, unsigned stride)
{
    unsigned total = 1u << __popc(m);
    for (unsigned s = start; s < total; s += stride) {
        float p = pbase;
        unsigned code = idx;
        unsigned sb = s;
        #pragma unroll
        for (int d = 0; d < DIM; d++) {
            if ((m >> d) & 1u) {
                if (sb & 1u) { p *= ratio[d]; code ^= (1u << d); }
                sb >>= 1u;
            }
        }
        unsigned long long f = __double2ull_rn((double)p * FIXSCALE);
        if (f) atomicAdd(&g_hist[code], f);
    }
}

// ---------------------------------------------------------------------------
__global__ void __launch_bounds__(128)
k_all(const float* __restrict__ z, const int* __restrict__ used,
      float* __restrict__ out) {
    int blk  = blockIdx.x;
    int tid  = threadIdx.x;
    int lane = tid & 31, wrp = tid >> 5;

    __shared__ unsigned s_bs[2048];

    if (blk < 32) {
        // ---- token work: 4 warps/block, thread = token -------------------
        int wg = blk * 4 + wrp;            // global token-warp 0..127
        int t  = wg * 32 + lane;
        int b  = t >> 10;
        int hw = t & 1023;
        const float* zp = z   + b * (DIM * HW) + hw;
        float*       qp = out + b * (DIM * HW) + hw;

        float com = 0.f, ent2 = 0.f, denom = 1.f;
        unsigned idx = 0u, mask = 0u;
        float ratio[DIM];

        #pragma unroll
        for (int d = 0; d < DIM; d++) {
            float zv = zp[d * HW];
            float q  = (zv > 0.f) ? 1.f : -1.f;
            qp[d * HW] = q;
            float df = zv - q;
            com += df * df;
            if (zv > 0.f) idx |= (1u << d);

            float ax = 400.f * fabsf(zv);
            float em = __expf(-ax);            // flip ratio po/pc
            ratio[d] = em;
            float op = 1.f + em;
            denom *= op;
            if (em >= EM_MIN) mask |= (1u << d);
            ent2 = fmaf(ax, __fdividef(em, op), ent2);
        }
        float pbase = __fdividef(1.f, denom);
        float ent   = __logf(denom) + ent2;    // + sum log1p(em), exact

        out[QELEMS + 3 + t] = (float)idx;
        atomicOr(&g_bitset[idx >> 5], 1u << (idx & 31u));

        #pragma unroll
        for (int o = 16; o; o >>= 1) {
            com += __shfl_down_sync(FULLM, com, o);
            ent += __shfl_down_sync(FULLM, ent, o);
        }
        if (lane == 0) { g_wcom[wg] = com; g_went[wg] = ent; }

        unsigned nsoft = __popc(mask);
        if (nsoft < 5)
            emit_subsets_strided(mask, pbase, idx, ratio, 0u, 1u);

        unsigned heavy = __ballot_sync(FULLM, nsoft >= 5);
        while (heavy) {
            int L = __ffs(heavy) - 1;
            heavy &= heavy - 1u;
            unsigned hm   = __shfl_sync(FULLM, mask,  L);
            float    hp   = __shfl_sync(FULLM, pbase, L);
            unsigned hidx = __shfl_sync(FULLM, idx,   L);
            float hr[DIM];
            #pragma unroll
            for (int d = 0; d < DIM; d++) hr[d] = __shfl_sync(FULLM, ratio[d], L);
            emit_subsets_strided(hm, hp, hidx, hr, (unsigned)lane, 32u);
        }
    } else {
        // ---- marking: used[4096:65536) = 61440 = 120 blk x 128 thr x 4 ---
        for (int i = tid; i < 2048; i += 128) s_bs[i] = 0u;
        __syncthreads();

        int m = (blk - 32) * 128 + tid;
        unsigned curw = 0xffffffffu, curm = 0u;
        #pragma unroll
        for (int it = 0; it < 4; it++) {
            unsigned v = ((unsigned)used[N_TOK + m + it * 15360]) & 65535u;
            unsigned w = v >> 5, mm = 1u << (v & 31u);
            if (w == curw) curm |= mm;
            else {
                if (curw != 0xffffffffu) atomicOr(&s_bs[curw], curm);
                curw = w; curm = mm;
            }
        }
        if (curw != 0xffffffffu) atomicOr(&s_bs[curw], curm);
        __syncthreads();

        for (int i = tid; i < 2048; i += 128) {
            unsigned v = s_bs[i];
            if (v) atomicOr(&g_bitset[i], v);
        }
    }

    // ---- ticket: threadFenceReduction pattern ----------------------------
    __shared__ int s_last;
    __threadfence();                       // all threads: release own writes
    __syncthreads();                       // block complete before arrival
    if (tid == 0) s_last = (atomicAdd(&g_ticket, 1u) == (unsigned)(NBLK - 1));
    __syncthreads();
    if (!s_last) return;                   // non-last blocks retire
    __threadfence();                       // acquire

    // ---- tail: full reduce on one block (128 threads), fixed order -------
    float ae = 0.f;
    #pragma unroll 8
    for (int k = 0; k < 128; k++) {
        int j = k * 128 + tid;
        unsigned long long hv = g_hist[j];
        if (hv) {
            g_hist[j] = 0ull;              // self-clean
            float avg = (float)((double)hv * (1.0 / FIXSCALE) * (1.0 / 4096.0));
            ae += -avg * __logf(avg + 1e-5f);
        }
    }
    int cnt = 0;
    #pragma unroll
    for (int k = 0; k < 16; k++) {
        int j = k * 128 + tid;
        unsigned wv = g_bitset[j];
        if (wv) { g_bitset[j] = 0u; cnt += __popc(wv); }
    }
    float cs = g_wcom[tid];
    float es = g_went[tid];

    __shared__ float r_ae[4], r_cs[4], r_es[4];
    __shared__ int   r_cn[4];
    #pragma unroll
    for (int o = 16; o; o >>= 1) {
        ae  += __shfl_down_sync(FULLM, ae,  o);
        cs  += __shfl_down_sync(FULLM, cs,  o);
        es  += __shfl_down_sync(FULLM, es,  o);
        cnt += __shfl_down_sync(FULLM, cnt, o);
    }
    if (lane == 0) { r_ae[wrp] = ae; r_cs[wrp] = cs; r_es[wrp] = es; r_cn[wrp] = cnt; }
    __syncthreads();
    if (tid == 0) {
        float avg_e    = (r_ae[0] + r_ae[1]) + (r_ae[2] + r_ae[3]);
        float comt     = (r_cs[0] + r_cs[1]) + (r_cs[2] + r_cs[3]);
        float entt     = (r_es[0] + r_es[1]) + (r_es[2] + r_es[3]);
        int   uc       = (r_cn[0] + r_cn[1]) + (r_cn[2] + r_cn[3]);
        float commit   = 0.25f * comt / (float)QELEMS;
        float sample_e = entt / (float)N_TOK;
        out[QELEMS + 0] = commit;
        out[QELEMS + 1] = 0.1f * (sample_e - avg_e);
        out[QELEMS + 2] = (float)uc / (float)NE;
        *(volatile unsigned int*)&g_ticket = 0u;   // reset for next replay
    }
}

// ---------------------------------------------------------------------------
extern "C" void kernel_launch(void* const* d_in, const int* in_sizes, int n_in,
                              void* d_out, int out_size) {
    const float* z    = (const float*)d_in[0];
    const int*   used = (const int*)d_in[2];
    float*       out  = (float*)d_out;

    k_all<<<NBLK, 128>>>(z, used, out);
}

// round 13
// speedup vs baseline: 3.2481x; 3.2481x over previous
#include <cuda_runtime.h>

// LFQ: z [4,14,32,32] f32. Codebook = all +-1 bit patterns -> T=0.01 softmax
// factorizes per bit. With em = expf(-400|z_d|): pc = 1/(1+em), po = em*pc,
// flip ratio po/pc = em. pbase = prod(pc) = 1/prod(1+em) (ONE divide);
// sum log1p(em) = logf(prod(1+em)) (ONE log). A soft bit matters only if
// em >= 2^-41 (else every subset's fixed-point emission rounds to 0) ->
// exact pruning; ~2 subsets/token scatter into a u64 fixed-point histogram
// (integer atomics commute => bit-deterministic).
//
// Two kernels (single-kernel tails measured 2-3x slower on this harness):
// k_main (tokens + ring marking) -> k_reduce (flat: warp-atomic fixed-point
// accumulation, ticket-elected tiny tail). All scratch self-cleans.
//
// Output (f32): quantized[57344], commit, entropy_loss, usage, idx_flat[4096].

#define N_TOK 4096
#define DIM   14
#define HW    1024
#define NE    16384
#define QELEMS (N_TOK * DIM)       // 57344
#define FIXSCALE 1099511627776.0   // 2^40
#define FULLM 0xffffffffu
#define EM_MIN 4.5474735088646412e-13f   // 2^-41

__device__ unsigned long long g_hist[NE];     // self-cleaned by k_reduce
__device__ unsigned int       g_bitset[2048]; // self-cleaned by k_reduce
__device__ float              g_wcom[128];    // rewritten every replay
__device__ float              g_went[128];
__device__ unsigned long long g_accA, g_accC, g_accE;  // fixed-point sums
__device__ int                g_accN;
__device__ unsigned int       g_ticket;       // reset by ticket block

// ---------------------------------------------------------------------------
__device__ __forceinline__ void emit_subsets_strided(
    unsigned m, float pbase, unsigned idx, const float* __restrict__ ratio,
    unsigned start, unsigned stride)
{
    unsigned total = 1u << __popc(m);
    for (unsigned s = start; s < total; s += stride) {
        float p = pbase;
        unsigned code = idx;
        unsigned sb = s;
        #pragma unroll
        for (int d = 0; d < DIM; d++) {
            if ((m >> d) & 1u) {
                if (sb & 1u) { p *= ratio[d]; code ^= (1u << d); }
                sb >>= 1u;
            }
        }
        unsigned long long f = __double2ull_rn((double)p * FIXSCALE);
        if (f) atomicAdd(&g_hist[code], f);
    }
}

// Blocks 0..127: one token-warp each (32 tokens). Blocks 128..367: marking.
__global__ void __launch_bounds__(32)
k_main(const float* __restrict__ z, const int* __restrict__ used,
       float* __restrict__ out) {
    int blk = blockIdx.x;
    int tid = threadIdx.x;                 // 32 threads

    if (blk < 128) {
        int t  = blk * 32 + tid;           // token id
        int b  = t >> 10;
        int hw = t & 1023;
        const float* zp = z   + b * (DIM * HW) + hw;
        float*       qp = out + b * (DIM * HW) + hw;

        float com = 0.f, ent2 = 0.f, denom = 1.f;
        unsigned idx = 0u, mask = 0u;
        float ratio[DIM];

        #pragma unroll
        for (int d = 0; d < DIM; d++) {
            float zv = zp[d * HW];
            float q  = (zv > 0.f) ? 1.f : -1.f;
            qp[d * HW] = q;
            float df = zv - q;
            com += df * df;
            if (zv > 0.f) idx |= (1u << d);

            float ax = 400.f * fabsf(zv);
            float em = __expf(-ax);            // flip ratio po/pc
            ratio[d] = em;
            float op = 1.f + em;
            denom *= op;
            if (em >= EM_MIN) mask |= (1u << d);
            ent2 = fmaf(ax, __fdividef(em, op), ent2);
        }
        float pbase = __fdividef(1.f, denom);
        float ent   = __logf(denom) + ent2;    // + sum log1p(em), exact

        out[QELEMS + 3 + t] = (float)idx;
        atomicOr(&g_bitset[idx >> 5], 1u << (idx & 31u));

        #pragma unroll
        for (int o = 16; o; o >>= 1) {
            com += __shfl_down_sync(FULLM, com, o);
            ent += __shfl_down_sync(FULLM, ent, o);
        }
        if (tid == 0) { g_wcom[blk] = com; g_went[blk] = ent; }

        unsigned nsoft = __popc(mask);
        if (nsoft < 5)
            emit_subsets_strided(mask, pbase, idx, ratio, 0u, 1u);

        unsigned heavy = __ballot_sync(FULLM, nsoft >= 5);
        while (heavy) {
            int L = __ffs(heavy) - 1;
            heavy &= heavy - 1u;
            unsigned hm   = __shfl_sync(FULLM, mask,  L);
            float    hp   = __shfl_sync(FULLM, pbase, L);
            unsigned hidx = __shfl_sync(FULLM, idx,   L);
            float hr[DIM];
            #pragma unroll
            for (int d = 0; d < DIM; d++) hr[d] = __shfl_sync(FULLM, ratio[d], L);
            emit_subsets_strided(hm, hp, hidx, hr, (unsigned)tid, 32u);
        }
    } else {
        // marking: used[4096:65536) = 61440 entries, 240 blocks x 32 thr x 8
        __shared__ unsigned s_bs[2048];
        for (int i = tid; i < 2048; i += 32) s_bs[i] = 0u;
        __syncthreads();

        int m = (blk - 128) * 32 + tid;
        unsigned curw = 0xffffffffu, curm = 0u;
        #pragma unroll
        for (int it = 0; it < 8; it++) {
            unsigned v = ((unsigned)used[N_TOK + m + it * 7680]) & 65535u;
            unsigned w = v >> 5, mm = 1u << (v & 31u);
            if (w == curw) curm |= mm;
            else {
                if (curw != 0xffffffffu) atomicOr(&s_bs[curw], curm);
                curw = w; curm = mm;
            }
        }
        if (curw != 0xffffffffu) atomicOr(&s_bs[curw], curm);
        __syncthreads();

        for (int i = tid; i < 2048; i += 32) {
            unsigned v = s_bs[i];
            if (v) atomicOr(&g_bitset[i], v);
        }
    }
}

// ---------------------------------------------------------------------------
// 128 blocks x 128 threads, flat: per-thread term -> warp shuffle-reduce ->
// ONE fixed-point u64 atomicAdd per warp (commutes => deterministic).
// Ticket-elected last block: tid 0 reads 4 accumulators, writes 3 scalars,
// resets everything for the next graph replay.
__global__ void __launch_bounds__(128)
k_reduce(float* __restrict__ out) {
    int tid  = threadIdx.x;
    int g    = blockIdx.x;
    int lane = tid & 31;

    // hist entropy: one code per thread, self-clean
    int j = g * 128 + tid;
    unsigned long long hv = g_hist[j];
    float ae = 0.f;
    if (hv) {
        g_hist[j] = 0ull;
        float avg = (float)((double)hv * (1.0 / FIXSCALE) * (1.0 / 4096.0));
        ae = -avg * __logf(avg + 1e-5f);
    }
    #pragma unroll
    for (int o = 16; o; o >>= 1) ae += __shfl_down_sync(FULLM, ae, o);
    if (lane == 0 && ae != 0.f)
        atomicAdd(&g_accA, (unsigned long long)__double2ll_rn((double)ae * FIXSCALE));

    // bitset popcount: 16 words per block (warp 0), self-clean
    if (tid < 16) {
        unsigned wv = g_bitset[g * 16 + tid];
        int cnt = 0;
        if (wv) { g_bitset[g * 16 + tid] = 0u; cnt = __popc(wv); }
        #pragma unroll
        for (int o = 8; o; o >>= 1) cnt += __shfl_down_sync(0xffffu, cnt, o);
        if (tid == 0 && cnt) atomicAdd(&g_accN, cnt);
    }

    // commit / sample-entropy partials: block 0 only
    if (g == 0) {
        float cs = g_wcom[tid];
        float es = g_went[tid];
        #pragma unroll
        for (int o = 16; o; o >>= 1) {
            cs += __shfl_down_sync(FULLM, cs, o);
            es += __shfl_down_sync(FULLM, es, o);
        }
        if (lane == 0) {
            atomicAdd(&g_accC, (unsigned long long)__double2ll_rn((double)cs * FIXSCALE));
            atomicAdd(&g_accE, (unsigned long long)__double2ll_rn((double)es * FIXSCALE));
        }
    }

    // ticket tail
    __shared__ int s_last;
    __threadfence();
    __syncthreads();
    if (tid == 0) s_last = (atomicAdd(&g_ticket, 1u) == 127u);
    __syncthreads();
    if (s_last && tid == 0) {
        __threadfence();
        long long a = (long long)*(volatile unsigned long long*)&g_accA;
        long long c = (long long)*(volatile unsigned long long*)&g_accC;
        long long e = (long long)*(volatile unsigned long long*)&g_accE;
        int       n = *(volatile int*)&g_accN;
        float avg_e    = (float)((double)a * (1.0 / FIXSCALE));
        float commit   = 0.25f * (float)((double)c * (1.0 / FIXSCALE)) / (float)QELEMS;
        float sample_e = (float)((double)e * (1.0 / FIXSCALE)) / (float)N_TOK;
        out[QELEMS + 0] = commit;
        out[QELEMS + 1] = 0.1f * (sample_e - avg_e);
        out[QELEMS + 2] = (float)n / (float)NE;
        // reset for next replay
        *(volatile unsigned long long*)&g_accA = 0ull;
        *(volatile unsigned long long*)&g_accC = 0ull;
        *(volatile unsigned long long*)&g_accE = 0ull;
        *(volatile int*)&g_accN                = 0;
        *(volatile unsigned int*)&g_ticket     = 0u;
    }
}

// ---------------------------------------------------------------------------
extern "C" void kernel_launch(void* const* d_in, const int* in_sizes, int n_in,
                              void* d_out, int out_size) {
    const float* z    = (const float*)d_in[0];
    const int*   used = (const int*)d_in[2];
    float*       out  = (float*)d_out;

    k_main<<<368, 32>>>(z, used, out);
    k_reduce<<<128, 128>>>(out);
}